// round 4
// baseline (speedup 1.0000x reference)
#include <cuda_runtime.h>
#include <cstdint>

// Problem constants (fixed shapes from setup_inputs)
#define HDIM 512
#define WDIM 512
#define HW   (HDIM*WDIM)          // 262144 floats per plane
#define HS 54
#define PH 51                     // HS - WIN + 1
#define NPOS (PH*PH)              // 2601
#define CROP 64
#define STRIDE_I 8                // floor((512-70)/54)
#define RF_I 70

#define TILE_FLOATS 8192          // 32 KB tile
#define TILE_BYTES  (TILE_FLOATS*4)
#define TILES_PER_PLANE (HW / TILE_FLOATS)     // 32
#define COPY_TILES  (16 * 6 * TILES_PER_PLANE) // 3072
#define CROP_BLOCKS (2 * 16 * 3 * CROP * CROP / 128)   // 3072 blocks of 128

// Per-batch coordinates (scratch: __device__ globals, no allocation)
__device__ int g_axH[64];   // ax[:,0] row coord
__device__ int g_axW[64];   // ax[:,1] col coord
__device__ int g_offE[64];  // plane-local element index of patched pixel

// ---------------------------------------------------------------------------
// Kernel 1: per-batch argmax over score_map[b,0,:51,:51], first-index tiebreak
// ---------------------------------------------------------------------------
__global__ void argmax_kernel(const float* __restrict__ score) {
    int b = blockIdx.x;
    __shared__ float svals[256];
    __shared__ int   sidx[256];
    int t = threadIdx.x;
    float best = -__int_as_float(0x7f800000);
    int bi = NPOS;
    for (int i = t; i < NPOS; i += 256) {
        int r = i / PH, c = i % PH;
        float v = score[b * (HS*HS) + r * HS + c];
        if (v > best) { best = v; bi = i; }
    }
    svals[t] = best; sidx[t] = bi;
    __syncthreads();
    for (int s = 128; s > 0; s >>= 1) {
        if (t < s) {
            float v2 = svals[t + s]; int i2 = sidx[t + s];
            if (v2 > svals[t] || (v2 == svals[t] && i2 < sidx[t])) {
                svals[t] = v2; sidx[t] = i2;
            }
        }
        __syncthreads();
    }
    if (t == 0) {
        int idx  = sidx[0];
        float bv = svals[0];
        int x = (bv > 0.0f) ? (idx / PH) : 0;
        int y = (bv > 0.0f) ? (idx % PH) : 0;
        int axH = x * STRIDE_I + RF_I;
        int axW = y * STRIDE_I + RF_I;
        g_axH[b] = axH;
        g_axW[b] = axW;
        g_offE[b] = axH * WDIM + axW;
    }
}

// ---------------------------------------------------------------------------
// PTX helpers (1D bulk async copy + mbarrier)
// ---------------------------------------------------------------------------
__device__ __forceinline__ uint32_t smem_u32(const void* p) {
    return (uint32_t)__cvta_generic_to_shared(p);
}

// ---------------------------------------------------------------------------
// Kernel 2 (fused): crop blocks [0, CROP_BLOCKS), TMA copy blocks after.
// ---------------------------------------------------------------------------
__global__ __launch_bounds__(128) void fused_kernel(
        const float* __restrict__ realAB,
        const float* __restrict__ fakeAB,
        const float* __restrict__ realB,
        const float* __restrict__ fakeB,
        float*       __restrict__ out_abm,
        float*       __restrict__ out_real,
        float*       __restrict__ out_fake)
{
    __shared__ __align__(16) float tile[TILE_FLOATS];
    __shared__ __align__(8)  uint64_t mbar;

    if (blockIdx.x >= CROP_BLOCKS) {
        // ---------------- TMA bulk copy + pixel patch ----------------
        if (threadIdx.x != 0) return;       // single-thread orchestration
        int t = blockIdx.x - CROP_BLOCKS;   // tile index [0, COPY_TILES)
        long long gbase = (long long)t * TILE_FLOATS;
        const float* src = realAB + gbase;
        float*       dst = out_abm + gbase;
        uint32_t s_tile = smem_u32(tile);
        uint32_t s_bar  = smem_u32(&mbar);

        // init mbarrier (count=1) and make it visible to the async proxy
        asm volatile("mbarrier.init.shared.b64 [%0], 1;" :: "r"(s_bar) : "memory");
        asm volatile("fence.proxy.async.shared::cta;" ::: "memory");

        // arrive + expect full tile bytes, then issue bulk load
        asm volatile("mbarrier.arrive.expect_tx.shared.b64 _, [%0], %1;"
                     :: "r"(s_bar), "r"((uint32_t)TILE_BYTES) : "memory");
        asm volatile(
            "cp.async.bulk.shared::cluster.global.mbarrier::complete_tx::bytes "
            "[%0], [%1], %2, [%3];"
            :: "r"(s_tile), "l"(src), "r"((uint32_t)TILE_BYTES), "r"(s_bar)
            : "memory");

        // wait for completion (phase 0)
        {
            uint32_t done;
            asm volatile(
                "{\n\t.reg .pred p;\n\t"
                "mbarrier.try_wait.parity.acquire.cta.shared::cta.b64 p, [%1], 0;\n\t"
                "selp.b32 %0, 1, 0, p;\n\t}"
                : "=r"(done) : "r"(s_bar) : "memory");
            if (!done) {
                asm volatile(
                    "{\n\t.reg .pred P1;\n\t"
                    "WL_%=:\n\t"
                    "mbarrier.try_wait.parity.acquire.cta.shared::cta.b64 P1, [%0], 0, 0x989680;\n\t"
                    "@P1 bra.uni WD_%=;\n\t"
                    "bra.uni WL_%=;\n\t"
                    "WD_%=:\n\t}"
                    :: "r"(s_bar) : "memory");
            }
        }

        // patch: at most one element per tile
        int b  = t / (6 * TILES_PER_PLANE);     // batch
        int tp = t & (TILES_PER_PLANE - 1);     // tile within plane
        int loffE = g_offE[b];                  // plane-local patched element
        int local = loffE - tp * TILE_FLOATS;
        if (local >= 0 && local < TILE_FLOATS) {
            int plane = t / TILES_PER_PLANE;    // (b*6 + c)
            tile[local] = fakeAB[(long long)plane * HW + loffE];
        }

        // order generic SMEM writes (patch) + loaded data before async-proxy read
        asm volatile("fence.proxy.async.shared::cta;" ::: "memory");

        // bulk store SMEM -> GMEM, then drain before block exit
        asm volatile(
            "cp.async.bulk.global.shared::cta.bulk_group [%0], [%1], %2;"
            :: "l"(dst), "r"(s_tile), "r"((uint32_t)TILE_BYTES) : "memory");
        asm volatile("cp.async.bulk.commit_group;" ::: "memory");
        asm volatile("cp.async.bulk.wait_group 0;" ::: "memory");
        return;
    }

    // ---------------- crop-and-resize (exact fp32 sequence) ----------------
    int gid = blockIdx.x * 128 + threadIdx.x;
    int per = 16 * 3 * CROP * CROP;
    int which = (gid >= per) ? 1 : 0;          // 0 = real, 1 = fake
    int lid = gid - which * per;

    int j = lid & (CROP - 1);
    int i = (lid >> 6) & (CROP - 1);
    int c = (lid >> 12) % 3;
    int b = lid / (3 * CROP * CROP);

    const float* img = (which ? fakeB : realB) + ((long long)b * 3 + c) * HW;
    float* dst = which ? out_fake : out_real;

    float axH = (float)g_axH[b];
    float axW = (float)g_axW[b];

    float nh  = __fdiv_rn(63.0f, (float)(HDIM - 1));
    float ny0 = __fdiv_rn(axH, (float)(HDIM - 1));
    float nx0 = __fdiv_rn(axW, (float)(WDIM - 1));
    float ny1 = __fadd_rn(ny0, nh);
    float nx1 = __fadd_rn(nx0, nh);
    float dy  = __fsub_rn(ny1, ny0);
    float dx  = __fsub_rn(nx1, nx0);

    float ys = __fadd_rn(__fmul_rn(ny0, (float)(HDIM - 1)),
                         __fdiv_rn(__fmul_rn(__fmul_rn((float)i, dy), (float)(HDIM - 1)),
                                   (float)(CROP - 1)));
    float xs = __fadd_rn(__fmul_rn(nx0, (float)(WDIM - 1)),
                         __fdiv_rn(__fmul_rn(__fmul_rn((float)j, dx), (float)(WDIM - 1)),
                                   (float)(CROP - 1)));

    bool vy = (ys >= 0.0f) && (ys <= (float)(HDIM - 1));
    bool vx = (xs >= 0.0f) && (xs <= (float)(WDIM - 1));

    float y0f = floorf(ys);
    float x0f = floorf(xs);
    int y0 = (int)fminf(fmaxf(y0f, 0.0f), (float)(HDIM - 1));
    int x0 = (int)fminf(fmaxf(x0f, 0.0f), (float)(WDIM - 1));
    int y1 = min(y0 + 1, HDIM - 1);
    int x1 = min(x0 + 1, WDIM - 1);

    float ly = __fsub_rn(ys, y0f);
    float lx = __fsub_rn(xs, x0f);

    float v00 = img[(long long)y0 * WDIM + x0];
    float v01 = img[(long long)y0 * WDIM + x1];
    float v10 = img[(long long)y1 * WDIM + x0];
    float v11 = img[(long long)y1 * WDIM + x1];

    float one_lx = __fsub_rn(1.0f, lx);
    float one_ly = __fsub_rn(1.0f, ly);
    float top = __fadd_rn(__fmul_rn(one_lx, v00), __fmul_rn(lx, v01));
    float bot = __fadd_rn(__fmul_rn(one_lx, v10), __fmul_rn(lx, v11));
    float val = __fadd_rn(__fmul_rn(one_ly, top), __fmul_rn(ly, bot));

    dst[lid] = (vy && vx) ? val : 0.0f;
}

// ---------------------------------------------------------------------------
extern "C" void kernel_launch(void* const* d_in, const int* in_sizes, int n_in,
                              void* d_out, int out_size) {
    const float* real_AB   = (const float*)d_in[0];
    const float* fake_AB   = (const float*)d_in[1];
    const float* score_map = (const float*)d_in[2];
    const float* real_B    = (const float*)d_in[3];
    const float* fake_B    = (const float*)d_in[4];
    float* out = (float*)d_out;

    int B = in_sizes[2] / (HS * HS);                           // 16
    long long abm_elems  = (long long)B * 6 * HW;              // 25,165,824
    long long crop_elems = (long long)B * 3 * CROP * CROP;     // 196,608

    float* out_abm  = out;
    float* out_real = out + abm_elems;
    float* out_fake = out + abm_elems + crop_elems;

    // 1. localize (crop + patch both depend on it; stream order = dependency)
    argmax_kernel<<<B, 256>>>(score_map);

    // 2. fused: crop blocks first (overlap), then TMA copy+patch blocks
    fused_kernel<<<CROP_BLOCKS + COPY_TILES, 128>>>(
        real_AB, fake_AB, real_B, fake_B,
        out_abm, out_real, out_fake);
}

// round 5
// speedup vs baseline: 1.1197x; 1.1197x over previous
#include <cuda_runtime.h>
#include <cstdint>

// Problem constants (fixed shapes from setup_inputs)
#define HDIM 512
#define WDIM 512
#define HW   (HDIM*WDIM)          // 262144 floats per plane
#define HS 54
#define PH 51                     // HS - WIN + 1
#define NPOS (PH*PH)              // 2601
#define CROP 64
#define STRIDE_I 8                // floor((512-70)/54)
#define RF_I 70

#define TILE_FLOATS 8192          // 32 KB tile
#define TILE_BYTES  (TILE_FLOATS*4)
#define TILES_PER_PLANE (HW / TILE_FLOATS)     // 32
#define COPY_TILES  (16 * 6 * TILES_PER_PLANE) // 3072
#define CROP_BLOCKS (2 * 16 * 3 * CROP * CROP / 128)   // 3072 blocks of 128

// Per-batch coordinates (scratch: __device__ globals, no allocation)
__device__ int g_axH[64];   // ax[:,0] row coord
__device__ int g_axW[64];   // ax[:,1] col coord
__device__ int g_offE[64];  // plane-local element index of patched pixel

// ---------------------------------------------------------------------------
// Kernel 1: per-batch argmax over score_map[b,0,:51,:51], first-index tiebreak
// ---------------------------------------------------------------------------
__global__ void argmax_kernel(const float* __restrict__ score) {
    int b = blockIdx.x;
    __shared__ float svals[256];
    __shared__ int   sidx[256];
    int t = threadIdx.x;
    float best = -__int_as_float(0x7f800000);
    int bi = NPOS;
    for (int i = t; i < NPOS; i += 256) {
        int r = i / PH, c = i % PH;
        float v = score[b * (HS*HS) + r * HS + c];
        if (v > best) { best = v; bi = i; }
    }
    svals[t] = best; sidx[t] = bi;
    __syncthreads();
    for (int s = 128; s > 0; s >>= 1) {
        if (t < s) {
            float v2 = svals[t + s]; int i2 = sidx[t + s];
            if (v2 > svals[t] || (v2 == svals[t] && i2 < sidx[t])) {
                svals[t] = v2; sidx[t] = i2;
            }
        }
        __syncthreads();
    }
    if (t == 0) {
        int idx  = sidx[0];
        float bv = svals[0];
        int x = (bv > 0.0f) ? (idx / PH) : 0;
        int y = (bv > 0.0f) ? (idx % PH) : 0;
        int axH = x * STRIDE_I + RF_I;
        int axW = y * STRIDE_I + RF_I;
        g_axH[b] = axH;
        g_axW[b] = axW;
        g_offE[b] = axH * WDIM + axW;
    }
}

// ---------------------------------------------------------------------------
__device__ __forceinline__ uint32_t smem_u32(const void* p) {
    return (uint32_t)__cvta_generic_to_shared(p);
}

// ---------------------------------------------------------------------------
// Kernel 2 (fused): crop blocks [0, CROP_BLOCKS), TMA copy blocks after.
// TMA ops carry L2::evict_first policy so the 200MB stream doesn't leave
// dirty lines thrashing L2 across back-to-back graph replays.
// ---------------------------------------------------------------------------
__global__ __launch_bounds__(128) void fused_kernel(
        const float* __restrict__ realAB,
        const float* __restrict__ fakeAB,
        const float* __restrict__ realB,
        const float* __restrict__ fakeB,
        float*       __restrict__ out_abm,
        float*       __restrict__ out_real,
        float*       __restrict__ out_fake)
{
    __shared__ __align__(16) float tile[TILE_FLOATS];
    __shared__ __align__(8)  uint64_t mbar;

    if (blockIdx.x >= CROP_BLOCKS) {
        // ---------------- TMA bulk copy + pixel patch ----------------
        if (threadIdx.x != 0) return;       // single-thread orchestration
        int t = blockIdx.x - CROP_BLOCKS;   // tile index [0, COPY_TILES)
        long long gbase = (long long)t * TILE_FLOATS;
        const float* src = realAB + gbase;
        float*       dst = out_abm + gbase;
        uint32_t s_tile = smem_u32(tile);
        uint32_t s_bar  = smem_u32(&mbar);

        // streaming L2 policy: evict-first for both directions
        uint64_t pol;
        asm volatile("createpolicy.fractional.L2::evict_first.b64 %0, 1.0;"
                     : "=l"(pol));

        // init mbarrier (count=1) and make it visible to the async proxy
        asm volatile("mbarrier.init.shared.b64 [%0], 1;" :: "r"(s_bar) : "memory");
        asm volatile("fence.proxy.async.shared::cta;" ::: "memory");

        // arrive + expect full tile bytes, then issue bulk load (evict_first)
        asm volatile("mbarrier.arrive.expect_tx.shared.b64 _, [%0], %1;"
                     :: "r"(s_bar), "r"((uint32_t)TILE_BYTES) : "memory");
        asm volatile(
            "cp.async.bulk.shared::cluster.global.mbarrier::complete_tx::bytes"
            ".L2::cache_hint [%0], [%1], %2, [%3], %4;"
            :: "r"(s_tile), "l"(src), "r"((uint32_t)TILE_BYTES), "r"(s_bar), "l"(pol)
            : "memory");

        // wait for completion (phase 0)
        {
            uint32_t done;
            asm volatile(
                "{\n\t.reg .pred p;\n\t"
                "mbarrier.try_wait.parity.acquire.cta.shared::cta.b64 p, [%1], 0;\n\t"
                "selp.b32 %0, 1, 0, p;\n\t}"
                : "=r"(done) : "r"(s_bar) : "memory");
            if (!done) {
                asm volatile(
                    "{\n\t.reg .pred P1;\n\t"
                    "WL_%=:\n\t"
                    "mbarrier.try_wait.parity.acquire.cta.shared::cta.b64 P1, [%0], 0, 0x989680;\n\t"
                    "@P1 bra.uni WD_%=;\n\t"
                    "bra.uni WL_%=;\n\t"
                    "WD_%=:\n\t}"
                    :: "r"(s_bar) : "memory");
            }
        }

        // patch: at most one element per tile
        int b  = t / (6 * TILES_PER_PLANE);     // batch
        int tp = t & (TILES_PER_PLANE - 1);     // tile within plane
        int loffE = g_offE[b];                  // plane-local patched element
        int local = loffE - tp * TILE_FLOATS;
        if (local >= 0 && local < TILE_FLOATS) {
            int plane = t / TILES_PER_PLANE;    // (b*6 + c)
            tile[local] = fakeAB[(long long)plane * HW + loffE];
        }

        // order generic SMEM writes (patch) before async-proxy read
        asm volatile("fence.proxy.async.shared::cta;" ::: "memory");

        // bulk store SMEM -> GMEM (evict_first), then drain before exit
        asm volatile(
            "cp.async.bulk.global.shared::cta.bulk_group.L2::cache_hint "
            "[%0], [%1], %2, %3;"
            :: "l"(dst), "r"(s_tile), "r"((uint32_t)TILE_BYTES), "l"(pol)
            : "memory");
        asm volatile("cp.async.bulk.commit_group;" ::: "memory");
        asm volatile("cp.async.bulk.wait_group 0;" ::: "memory");
        return;
    }

    // ---------------- crop-and-resize (exact fp32 sequence) ----------------
    int gid = blockIdx.x * 128 + threadIdx.x;
    int per = 16 * 3 * CROP * CROP;
    int which = (gid >= per) ? 1 : 0;          // 0 = real, 1 = fake
    int lid = gid - which * per;

    int j = lid & (CROP - 1);
    int i = (lid >> 6) & (CROP - 1);
    int c = (lid >> 12) % 3;
    int b = lid / (3 * CROP * CROP);

    const float* img = (which ? fakeB : realB) + ((long long)b * 3 + c) * HW;
    float* dst = which ? out_fake : out_real;

    float axH = (float)g_axH[b];
    float axW = (float)g_axW[b];

    float nh  = __fdiv_rn(63.0f, (float)(HDIM - 1));
    float ny0 = __fdiv_rn(axH, (float)(HDIM - 1));
    float nx0 = __fdiv_rn(axW, (float)(WDIM - 1));
    float ny1 = __fadd_rn(ny0, nh);
    float nx1 = __fadd_rn(nx0, nh);
    float dy  = __fsub_rn(ny1, ny0);
    float dx  = __fsub_rn(nx1, nx0);

    float ys = __fadd_rn(__fmul_rn(ny0, (float)(HDIM - 1)),
                         __fdiv_rn(__fmul_rn(__fmul_rn((float)i, dy), (float)(HDIM - 1)),
                                   (float)(CROP - 1)));
    float xs = __fadd_rn(__fmul_rn(nx0, (float)(WDIM - 1)),
                         __fdiv_rn(__fmul_rn(__fmul_rn((float)j, dx), (float)(WDIM - 1)),
                                   (float)(CROP - 1)));

    bool vy = (ys >= 0.0f) && (ys <= (float)(HDIM - 1));
    bool vx = (xs >= 0.0f) && (xs <= (float)(WDIM - 1));

    float y0f = floorf(ys);
    float x0f = floorf(xs);
    int y0 = (int)fminf(fmaxf(y0f, 0.0f), (float)(HDIM - 1));
    int x0 = (int)fminf(fmaxf(x0f, 0.0f), (float)(WDIM - 1));
    int y1 = min(y0 + 1, HDIM - 1);
    int x1 = min(x0 + 1, WDIM - 1);

    float ly = __fsub_rn(ys, y0f);
    float lx = __fsub_rn(xs, x0f);

    float v00 = img[(long long)y0 * WDIM + x0];
    float v01 = img[(long long)y0 * WDIM + x1];
    float v10 = img[(long long)y1 * WDIM + x0];
    float v11 = img[(long long)y1 * WDIM + x1];

    float one_lx = __fsub_rn(1.0f, lx);
    float one_ly = __fsub_rn(1.0f, ly);
    float top = __fadd_rn(__fmul_rn(one_lx, v00), __fmul_rn(lx, v01));
    float bot = __fadd_rn(__fmul_rn(one_lx, v10), __fmul_rn(lx, v11));
    float val = __fadd_rn(__fmul_rn(one_ly, top), __fmul_rn(ly, bot));

    dst[lid] = (vy && vx) ? val : 0.0f;
}

// ---------------------------------------------------------------------------
extern "C" void kernel_launch(void* const* d_in, const int* in_sizes, int n_in,
                              void* d_out, int out_size) {
    const float* real_AB   = (const float*)d_in[0];
    const float* fake_AB   = (const float*)d_in[1];
    const float* score_map = (const float*)d_in[2];
    const float* real_B    = (const float*)d_in[3];
    const float* fake_B    = (const float*)d_in[4];
    float* out = (float*)d_out;

    int B = in_sizes[2] / (HS * HS);                           // 16
    long long abm_elems  = (long long)B * 6 * HW;              // 25,165,824
    long long crop_elems = (long long)B * 3 * CROP * CROP;     // 196,608

    float* out_abm  = out;
    float* out_real = out + abm_elems;
    float* out_fake = out + abm_elems + crop_elems;

    // 1. localize (crop + patch both depend on it; stream order = dependency)
    argmax_kernel<<<B, 256>>>(score_map);

    // 2. fused: crop blocks first (overlap), then TMA copy+patch blocks
    fused_kernel<<<CROP_BLOCKS + COPY_TILES, 128>>>(
        real_AB, fake_AB, real_B, fake_B,
        out_abm, out_real, out_fake);
}

// round 6
// speedup vs baseline: 1.1474x; 1.0247x over previous
#include <cuda_runtime.h>
#include <cstdint>

// Problem constants (fixed shapes from setup_inputs)
#define HDIM 512
#define WDIM 512
#define HW   (HDIM*WDIM)          // 262144 floats per plane
#define HS 54
#define PH 51                     // HS - WIN + 1
#define NPOS (PH*PH)              // 2601
#define CROP 64
#define STRIDE_I 8                // floor((512-70)/54)
#define RF_I 70

// Pipelined copy geometry
#define TILE_FLOATS 2048          // 8 KB tile
#define TILE_BYTES  (TILE_FLOATS*4)
#define TILES_PER_PLANE (HW / TILE_FLOATS)       // 128
#define COPY_TILES  (16 * 6 * TILES_PER_PLANE)   // 12288
#define NCOPY       768                          // persistent copy blocks
#define TPB         (COPY_TILES / NCOPY)         // 16 tiles per block
#define NBUF        3                            // ring buffers (lookahead 2)

#define CROP_BLOCKS (2 * 16 * 3 * CROP * CROP / 128)   // 3072 blocks of 128

// Per-batch coordinates (scratch: __device__ globals, no allocation)
__device__ int g_axH[64];   // ax[:,0] row coord
__device__ int g_axW[64];   // ax[:,1] col coord
__device__ int g_offE[64];  // plane-local element index of patched pixel

// ---------------------------------------------------------------------------
// Kernel 1: per-batch argmax over score_map[b,0,:51,:51], first-index tiebreak
// ---------------------------------------------------------------------------
__global__ void argmax_kernel(const float* __restrict__ score) {
    int b = blockIdx.x;
    __shared__ float svals[256];
    __shared__ int   sidx[256];
    int t = threadIdx.x;
    float best = -__int_as_float(0x7f800000);
    int bi = NPOS;
    for (int i = t; i < NPOS; i += 256) {
        int r = i / PH, c = i % PH;
        float v = score[b * (HS*HS) + r * HS + c];
        if (v > best) { best = v; bi = i; }
    }
    svals[t] = best; sidx[t] = bi;
    __syncthreads();
    for (int s = 128; s > 0; s >>= 1) {
        if (t < s) {
            float v2 = svals[t + s]; int i2 = sidx[t + s];
            if (v2 > svals[t] || (v2 == svals[t] && i2 < sidx[t])) {
                svals[t] = v2; sidx[t] = i2;
            }
        }
        __syncthreads();
    }
    if (t == 0) {
        int idx  = sidx[0];
        float bv = svals[0];
        int x = (bv > 0.0f) ? (idx / PH) : 0;
        int y = (bv > 0.0f) ? (idx % PH) : 0;
        int axH = x * STRIDE_I + RF_I;
        int axW = y * STRIDE_I + RF_I;
        g_axH[b] = axH;
        g_axW[b] = axW;
        g_offE[b] = axH * WDIM + axW;
    }
}

// ---------------------------------------------------------------------------
__device__ __forceinline__ uint32_t smem_u32(const void* p) {
    return (uint32_t)__cvta_generic_to_shared(p);
}

__device__ __forceinline__ void bulk_load(uint32_t s_dst, const void* gsrc,
                                          uint32_t bytes, uint32_t s_bar, uint64_t pol) {
    asm volatile("mbarrier.arrive.expect_tx.shared.b64 _, [%0], %1;"
                 :: "r"(s_bar), "r"(bytes) : "memory");
    asm volatile(
        "cp.async.bulk.shared::cluster.global.mbarrier::complete_tx::bytes"
        ".L2::cache_hint [%0], [%1], %2, [%3], %4;"
        :: "r"(s_dst), "l"(gsrc), "r"(bytes), "r"(s_bar), "l"(pol)
        : "memory");
}

__device__ __forceinline__ void mbar_wait(uint32_t s_bar, uint32_t phase) {
    uint32_t done;
    asm volatile(
        "{\n\t.reg .pred p;\n\t"
        "mbarrier.try_wait.parity.acquire.cta.shared::cta.b64 p, [%1], %2;\n\t"
        "selp.b32 %0, 1, 0, p;\n\t}"
        : "=r"(done) : "r"(s_bar), "r"(phase) : "memory");
    if (!done) {
        asm volatile(
            "{\n\t.reg .pred P1;\n\t"
            "WL_%=:\n\t"
            "mbarrier.try_wait.parity.acquire.cta.shared::cta.b64 P1, [%0], %1, 0x989680;\n\t"
            "@P1 bra.uni WD_%=;\n\t"
            "bra.uni WL_%=;\n\t"
            "WD_%=:\n\t}"
            :: "r"(s_bar), "r"(phase) : "memory");
    }
}

// ---------------------------------------------------------------------------
// Kernel 2 (fused): crop blocks [0, CROP_BLOCKS); persistent pipelined TMA
// copy blocks after. 3-buffer ring, lookahead-2 loads, async bulk stores.
// ---------------------------------------------------------------------------
__global__ __launch_bounds__(128) void fused_kernel(
        const float* __restrict__ realAB,
        const float* __restrict__ fakeAB,
        const float* __restrict__ realB,
        const float* __restrict__ fakeB,
        float*       __restrict__ out_abm,
        float*       __restrict__ out_real,
        float*       __restrict__ out_fake)
{
    __shared__ __align__(16) float bufs[NBUF][TILE_FLOATS];
    __shared__ __align__(8)  uint64_t mbar[NBUF];

    if (blockIdx.x >= CROP_BLOCKS) {
        // ---------------- persistent pipelined TMA copy + patch ----------------
        if (threadIdx.x != 0) return;       // single-thread orchestration
        int cb = blockIdx.x - CROP_BLOCKS;  // 0..NCOPY-1
        int t0 = cb * TPB;

        uint64_t pol;
        asm volatile("createpolicy.fractional.L2::evict_first.b64 %0, 1.0;"
                     : "=l"(pol));

        uint32_t s_bar0 = smem_u32(&mbar[0]);
        uint32_t s_buf0 = smem_u32(&bufs[0][0]);

        #pragma unroll
        for (int k = 0; k < NBUF; k++)
            asm volatile("mbarrier.init.shared.b64 [%0], 1;"
                         :: "r"(s_bar0 + k * 8) : "memory");
        asm volatile("fence.proxy.async.shared::cta;" ::: "memory");

        // prologue: issue loads for tiles 0,1
        #pragma unroll
        for (int k = 0; k < 2; k++)
            bulk_load(s_buf0 + k * TILE_BYTES,
                      realAB + (long long)(t0 + k) * TILE_FLOATS,
                      TILE_BYTES, s_bar0 + k * 8, pol);

        for (int i = 0; i < TPB; i++) {
            int bi = i % NBUF;
            uint32_t ph = (uint32_t)((i / NBUF) & 1);
            mbar_wait(s_bar0 + bi * 8, ph);

            // patch: at most one element per tile
            int t  = t0 + i;
            int b  = t / (6 * TILES_PER_PLANE);
            int tp = t & (TILES_PER_PLANE - 1);
            int loffE = g_offE[b];
            int local = loffE - tp * TILE_FLOATS;
            if (local >= 0 && local < TILE_FLOATS) {
                int plane = t / TILES_PER_PLANE;
                bufs[bi][local] = fakeAB[(long long)plane * HW + loffE];
            }
            asm volatile("fence.proxy.async.shared::cta;" ::: "memory");

            // async bulk store of tile i
            asm volatile(
                "cp.async.bulk.global.shared::cta.bulk_group.L2::cache_hint "
                "[%0], [%1], %2, %3;"
                :: "l"(out_abm + (long long)t * TILE_FLOATS),
                   "r"(s_buf0 + bi * TILE_BYTES), "r"((uint32_t)TILE_BYTES), "l"(pol)
                : "memory");
            asm volatile("cp.async.bulk.commit_group;" ::: "memory");

            // lookahead-2 load into buffer (i+2)%3 once store (i-1) drained
            if (i + 2 < TPB) {
                asm volatile("cp.async.bulk.wait_group 1;" ::: "memory");
                int j  = i + 2;
                int bj = j % NBUF;
                bulk_load(s_buf0 + bj * TILE_BYTES,
                          realAB + (long long)(t0 + j) * TILE_FLOATS,
                          TILE_BYTES, s_bar0 + bj * 8, pol);
            }
        }
        // drain all stores before smem is released
        asm volatile("cp.async.bulk.wait_group 0;" ::: "memory");
        return;
    }

    // ---------------- crop-and-resize (exact fp32 sequence) ----------------
    int gid = blockIdx.x * 128 + threadIdx.x;
    int per = 16 * 3 * CROP * CROP;
    int which = (gid >= per) ? 1 : 0;          // 0 = real, 1 = fake
    int lid = gid - which * per;

    int j = lid & (CROP - 1);
    int i = (lid >> 6) & (CROP - 1);
    int c = (lid >> 12) % 3;
    int b = lid / (3 * CROP * CROP);

    const float* img = (which ? fakeB : realB) + ((long long)b * 3 + c) * HW;
    float* dst = which ? out_fake : out_real;

    float axH = (float)g_axH[b];
    float axW = (float)g_axW[b];

    float nh  = __fdiv_rn(63.0f, (float)(HDIM - 1));
    float ny0 = __fdiv_rn(axH, (float)(HDIM - 1));
    float nx0 = __fdiv_rn(axW, (float)(WDIM - 1));
    float ny1 = __fadd_rn(ny0, nh);
    float nx1 = __fadd_rn(nx0, nh);
    float dy  = __fsub_rn(ny1, ny0);
    float dx  = __fsub_rn(nx1, nx0);

    float ys = __fadd_rn(__fmul_rn(ny0, (float)(HDIM - 1)),
                         __fdiv_rn(__fmul_rn(__fmul_rn((float)i, dy), (float)(HDIM - 1)),
                                   (float)(CROP - 1)));
    float xs = __fadd_rn(__fmul_rn(nx0, (float)(WDIM - 1)),
                         __fdiv_rn(__fmul_rn(__fmul_rn((float)j, dx), (float)(WDIM - 1)),
                                   (float)(CROP - 1)));

    bool vy = (ys >= 0.0f) && (ys <= (float)(HDIM - 1));
    bool vx = (xs >= 0.0f) && (xs <= (float)(WDIM - 1));

    float y0f = floorf(ys);
    float x0f = floorf(xs);
    int y0 = (int)fminf(fmaxf(y0f, 0.0f), (float)(HDIM - 1));
    int x0 = (int)fminf(fmaxf(x0f, 0.0f), (float)(WDIM - 1));
    int y1 = min(y0 + 1, HDIM - 1);
    int x1 = min(x0 + 1, WDIM - 1);

    float ly = __fsub_rn(ys, y0f);
    float lx = __fsub_rn(xs, x0f);

    float v00 = img[(long long)y0 * WDIM + x0];
    float v01 = img[(long long)y0 * WDIM + x1];
    float v10 = img[(long long)y1 * WDIM + x0];
    float v11 = img[(long long)y1 * WDIM + x1];

    float one_lx = __fsub_rn(1.0f, lx);
    float one_ly = __fsub_rn(1.0f, ly);
    float top = __fadd_rn(__fmul_rn(one_lx, v00), __fmul_rn(lx, v01));
    float bot = __fadd_rn(__fmul_rn(one_lx, v10), __fmul_rn(lx, v11));
    float val = __fadd_rn(__fmul_rn(one_ly, top), __fmul_rn(ly, bot));

    dst[lid] = (vy && vx) ? val : 0.0f;
}

// ---------------------------------------------------------------------------
extern "C" void kernel_launch(void* const* d_in, const int* in_sizes, int n_in,
                              void* d_out, int out_size) {
    const float* real_AB   = (const float*)d_in[0];
    const float* fake_AB   = (const float*)d_in[1];
    const float* score_map = (const float*)d_in[2];
    const float* real_B    = (const float*)d_in[3];
    const float* fake_B    = (const float*)d_in[4];
    float* out = (float*)d_out;

    int B = in_sizes[2] / (HS * HS);                           // 16
    long long abm_elems  = (long long)B * 6 * HW;              // 25,165,824
    long long crop_elems = (long long)B * 3 * CROP * CROP;     // 196,608

    float* out_abm  = out;
    float* out_real = out + abm_elems;
    float* out_fake = out + abm_elems + crop_elems;

    // 1. localize (crop + patch both depend on it; stream order = dependency)
    argmax_kernel<<<B, 256>>>(score_map);

    // 2. fused: crop blocks first (overlap), then persistent TMA copy blocks
    fused_kernel<<<CROP_BLOCKS + NCOPY, 128>>>(
        real_AB, fake_AB, real_B, fake_B,
        out_abm, out_real, out_fake);
}